// round 1
// baseline (speedup 1.0000x reference)
#include <cuda_runtime.h>

#define Bb   1024
#define Nn   512
#define Mm   128
#define CD   1024
#define ODIM 390

// scratch for fc projection output (allowed: __device__ global array)
__device__ float g_o[Bb * ODIM];

// ------------------------------------------------------------------
// Kernel 1: o = hid @ W_fc^T + b_fc      [1024 x 390]
// Tiled fp32 GEMM: BM=BN=BK=32, 64 threads, 4x4 microtile per thread.
// ------------------------------------------------------------------
#define BM 32
#define BN 32
#define BK 32

__global__ __launch_bounds__(64) void fc_gemm(const float* __restrict__ hid,
                                              const float* __restrict__ W,
                                              const float* __restrict__ bias,
                                              float* __restrict__ o) {
    __shared__ float hs[BM][BK + 4];   // +4 keeps 16B alignment, reduces conflicts
    __shared__ float ws[BN][BK + 4];

    const int b0 = blockIdx.x * BM;
    const int j0 = blockIdx.y * BN;
    const int tid = threadIdx.x;
    const int ty = tid >> 3;     // 0..7  -> 4 b-rows each
    const int tx = tid & 7;      // 0..7  -> 4 j-cols each

    float acc[4][4] = {};

    for (int kc = 0; kc < CD; kc += BK) {
        __syncthreads();
        #pragma unroll
        for (int i = 0; i < 4; i++) {
            int f4 = tid + 64 * i;          // 0..255 float4 slots (32x32 tile)
            int r  = f4 >> 3;               // tile row 0..31
            int kq = (f4 & 7) * 4;          // k offset 0..28
            float4 hv = *(const float4*)&hid[(size_t)(b0 + r) * CD + kc + kq];
            *(float4*)&hs[r][kq] = hv;
            int j = j0 + r;
            float4 wv = make_float4(0.f, 0.f, 0.f, 0.f);
            if (j < ODIM)
                wv = *(const float4*)&W[(size_t)j * CD + kc + kq];
            *(float4*)&ws[r][kq] = wv;
        }
        __syncthreads();

        #pragma unroll
        for (int kk = 0; kk < BK; kk += 4) {
            float4 hv[4], wv[4];
            #pragma unroll
            for (int i = 0; i < 4; i++) hv[i] = *(float4*)&hs[ty * 4 + i][kk];
            #pragma unroll
            for (int i = 0; i < 4; i++) wv[i] = *(float4*)&ws[tx * 4 + i][kk];
            #pragma unroll
            for (int i = 0; i < 4; i++)
                #pragma unroll
                for (int j = 0; j < 4; j++) {
                    acc[i][j] += hv[i].x * wv[j].x;
                    acc[i][j] += hv[i].y * wv[j].y;
                    acc[i][j] += hv[i].z * wv[j].z;
                    acc[i][j] += hv[i].w * wv[j].w;
                }
        }
    }

    #pragma unroll
    for (int i = 0; i < 4; i++) {
        int bb = b0 + ty * 4 + i;
        #pragma unroll
        for (int j = 0; j < 4; j++) {
            int jj = j0 + tx * 4 + j;
            if (jj < ODIM)
                o[(size_t)bb * ODIM + jj] = acc[i][j] + bias[jj];
        }
    }
}

// ------------------------------------------------------------------
// Kernel 2: fused NTM write head, one CTA per batch row b.
// ------------------------------------------------------------------
__device__ __forceinline__ float sigmoidf_(float x) { return 1.f / (1.f + expf(-x)); }
__device__ __forceinline__ float softplusf_(float x) {
    return fmaxf(x, 0.f) + log1pf(expf(-fabsf(x)));
}

__device__ __forceinline__ float block_reduce_sum(float v, float* red) {
    int lane = threadIdx.x & 31, wid = threadIdx.x >> 5;
    #pragma unroll
    for (int off = 16; off; off >>= 1) v += __shfl_xor_sync(0xffffffffu, v, off);
    if (lane == 0) red[wid] = v;
    __syncthreads();
    if (wid == 0) {
        float x = (lane < 16) ? red[lane] : 0.f;
        #pragma unroll
        for (int off = 8; off; off >>= 1) x += __shfl_xor_sync(0xffffffffu, x, off);
        if (lane == 0) red[16] = x;
    }
    __syncthreads();
    float r = red[16];
    __syncthreads();
    return r;
}

__device__ __forceinline__ float block_reduce_max(float v, float* red) {
    int lane = threadIdx.x & 31, wid = threadIdx.x >> 5;
    #pragma unroll
    for (int off = 16; off; off >>= 1)
        v = fmaxf(v, __shfl_xor_sync(0xffffffffu, v, off));
    if (lane == 0) red[wid] = v;
    __syncthreads();
    if (wid == 0) {
        float x = (lane < 16) ? red[lane] : -3.4e38f;
        #pragma unroll
        for (int off = 8; off; off >>= 1)
            x = fmaxf(x, __shfl_xor_sync(0xffffffffu, x, off));
        if (lane == 0) red[16] = x;
    }
    __syncthreads();
    float r = red[16];
    __syncthreads();
    return r;
}

__global__ __launch_bounds__(512) void ntm_main(const float* __restrict__ w_pre,
                                                const float* __restrict__ memory,
                                                float* __restrict__ out_w,
                                                float* __restrict__ out_mem) {
    __shared__ float k_e[Mm], evec[Mm], avec[Mm];
    __shared__ float Ksm[Nn];     // K values, later reused for final w
    __shared__ float wgsm[Nn];
    __shared__ float red[17];
    __shared__ float s_beta, s_g, s_s0, s_s1, s_s2, s_gamma, s_knorm;

    const int b = blockIdx.x;
    const int tid = threadIdx.x;
    const int lane = tid & 31, wid = tid >> 5;
    const float* __restrict__ ob = g_o + (size_t)b * ODIM;

    // ---- phase 0: head params + activations ----
    if (tid < Mm) {
        k_e[tid]  = ob[tid] + 1e-16f;            // k + eps
        evec[tid] = sigmoidf_(ob[134 + tid]);    // erase
        avec[tid] = ob[262 + tid];               // add
    }
    if (tid == 128) {
        s_beta = softplusf_(ob[128]);
        s_g    = sigmoidf_(ob[129]);
        float x0 = ob[130], x1 = ob[131], x2 = ob[132];
        float mx = fmaxf(x0, fmaxf(x1, x2));
        float e0 = expf(x0 - mx), e1 = expf(x1 - mx), e2 = expf(x2 - mx);
        float inv = 1.f / (e0 + e1 + e2);
        s_s0 = e0 * inv; s_s1 = e1 * inv; s_s2 = e2 * inv;
        s_gamma = 1.f + softplusf_(ob[133]);
    }
    __syncthreads();

    // ||k_e||
    {
        float v = (tid < Mm) ? k_e[tid] * k_e[tid] : 0.f;
        float ss = block_reduce_sum(v, red);
        if (tid == 0) s_knorm = sqrtf(ss);
        __syncthreads();
    }
    const float knorm = s_knorm;
    const float4 kv = *(const float4*)&k_e[lane * 4];
    const float* __restrict__ memb = memory + (size_t)b * Nn * Mm;

    // ---- phase 1: cosine similarity K[n], one warp per row, 4 rows in flight ----
    #pragma unroll 1
    for (int g4 = 0; g4 < (Nn / 16) / 4; g4++) {
        int n0 = wid + (g4 * 4 + 0) * 16;
        int n1 = wid + (g4 * 4 + 1) * 16;
        int n2 = wid + (g4 * 4 + 2) * 16;
        int n3 = wid + (g4 * 4 + 3) * 16;
        float4 m0 = __ldg((const float4*)(memb + (size_t)n0 * Mm) + lane);
        float4 m1 = __ldg((const float4*)(memb + (size_t)n1 * Mm) + lane);
        float4 m2 = __ldg((const float4*)(memb + (size_t)n2 * Mm) + lane);
        float4 m3 = __ldg((const float4*)(memb + (size_t)n3 * Mm) + lane);

        #pragma unroll
        for (int q = 0; q < 4; q++) {
            float4 m4 = (q == 0) ? m0 : (q == 1) ? m1 : (q == 2) ? m2 : m3;
            int n = (q == 0) ? n0 : (q == 1) ? n1 : (q == 2) ? n2 : n3;
            float x0 = m4.x + 1e-16f, x1 = m4.y + 1e-16f;
            float x2 = m4.z + 1e-16f, x3 = m4.w + 1e-16f;
            float num = x0 * kv.x + x1 * kv.y + x2 * kv.z + x3 * kv.w;
            float ss  = x0 * x0 + x1 * x1 + x2 * x2 + x3 * x3;
            #pragma unroll
            for (int off = 16; off; off >>= 1) {
                num += __shfl_xor_sync(0xffffffffu, num, off);
                ss  += __shfl_xor_sync(0xffffffffu, ss, off);
            }
            if (lane == 0) {
                float denom = sqrtf(ss) * knorm;
                Ksm[n] = num / fmaxf(denom, 1e-8f);
            }
        }
    }
    __syncthreads();

    // ---- phase 2: softmax + interpolate + shift + sharpen + normalize ----
    const int n = tid;
    float bk = s_beta * Ksm[n];
    float mx = block_reduce_max(bk, red);
    float p = expf(bk - mx);
    float psum = block_reduce_sum(p, red);
    float wc = p / psum;
    float g = s_g;
    float wg = g * wc + (1.f - g) * __ldg(&w_pre[(size_t)b * Nn + n]);
    wgsm[n] = wg;
    __syncthreads();
    float wsh = s_s0 * wgsm[(n + Nn - 1) & (Nn - 1)]
              + s_s1 * wg
              + s_s2 * wgsm[(n + 1) & (Nn - 1)];
    float wsp = powf(wsh, s_gamma);
    float wsum = block_reduce_sum(wsp, red);
    float w = wsp / (wsum + 1e-16f);
    Ksm[n] = w;                                   // reuse as final w
    out_w[(size_t)b * Nn + n] = w;
    __syncthreads();

    // ---- phase 3: erase/add write ----
    float* __restrict__ omem = out_mem + (size_t)b * Nn * Mm;
    #pragma unroll 4
    for (int idx = tid; idx < (Nn * Mm) / 4; idx += 512) {
        int nr = idx >> 5;           // 32 float4 per row
        int mq = (idx & 31) * 4;
        float wn = Ksm[nr];
        float4 mv = __ldg((const float4*)(memb + (size_t)nr * Mm + mq));
        float4 ev = *(const float4*)&evec[mq];
        float4 av = *(const float4*)&avec[mq];
        float4 r;
        r.x = mv.x * (1.f - wn * ev.x) + wn * av.x;
        r.y = mv.y * (1.f - wn * ev.y) + wn * av.y;
        r.z = mv.z * (1.f - wn * ev.z) + wn * av.z;
        r.w = mv.w * (1.f - wn * ev.w) + wn * av.w;
        *(float4*)(omem + (size_t)nr * Mm + mq) = r;
    }
}

// ------------------------------------------------------------------
extern "C" void kernel_launch(void* const* d_in, const int* in_sizes, int n_in,
                              void* d_out, int out_size) {
    const float* hid    = (const float*)d_in[0];
    const float* w_pre  = (const float*)d_in[1];
    const float* memory = (const float*)d_in[2];
    const float* W_fc   = (const float*)d_in[3];
    const float* b_fc   = (const float*)d_in[4];
    float* out = (float*)d_out;

    float* o_ptr = nullptr;
    cudaGetSymbolAddress((void**)&o_ptr, g_o);

    fc_gemm<<<dim3(Bb / BM, (ODIM + BN - 1) / BN), 64>>>(hid, W_fc, b_fc, o_ptr);
    ntm_main<<<Bb, 512>>>(w_pre, memory, out, out + (size_t)Bb * Nn);
}

// round 2
// speedup vs baseline: 1.0545x; 1.0545x over previous
#include <cuda_runtime.h>

#define Bb   1024
#define Nn   512
#define Mm   128
#define CD   1024
#define ODIM 390

// scratch (allowed: __device__ global arrays)
__device__ float g_o[Bb * ODIM];    // activated head params
__device__ float g_e[Bb * Mm];      // sigmoid(e), 16B-aligned rows
__device__ float g_a[Bb * Mm];      // add vector, 16B-aligned rows

__device__ __forceinline__ float sigmoidf_(float x) { return 1.f / (1.f + expf(-x)); }
__device__ __forceinline__ float softplusf_(float x) {
    return fmaxf(x, 0.f) + log1pf(expf(-fabsf(x)));
}

// ------------------------------------------------------------------
// Kernel 1: o = act(hid @ W_fc^T + b_fc)
// 256 threads, BM=BN=64, BK=16, 4x4 microtile, reg-prefetch double buffer.
// Epilogue applies per-column activations and scatters e/a to aligned scratch.
// ------------------------------------------------------------------
#define BM 64
#define BN 64
#define BK 16

__global__ __launch_bounds__(256) void fc_gemm(const float* __restrict__ hid,
                                               const float* __restrict__ W,
                                               const float* __restrict__ bias,
                                               float* __restrict__ o) {
    __shared__ float as[BK][BM + 4];   // [k][m]
    __shared__ float ws[BK][BN + 4];   // [k][n]

    const int b0 = blockIdx.x * BM;
    const int j0 = blockIdx.y * BN;
    const int tid = threadIdx.x;
    const int ty = tid >> 4;        // 0..15 -> 4 m-rows
    const int tx = tid & 15;        // 0..15 -> 4 n-cols
    const int r  = tid >> 2;        // 0..63 load row
    const int q  = (tid & 3) * 4;   // 0..12 k-offset

    float acc[4][4] = {};

    // prefetch first tiles into registers
    float4 ha = *(const float4*)&hid[(size_t)(b0 + r) * CD + q];
    float4 wa = make_float4(0.f, 0.f, 0.f, 0.f);
    if (j0 + r < ODIM)
        wa = *(const float4*)&W[(size_t)(j0 + r) * CD + q];

    for (int kc = 0; kc < CD; kc += BK) {
        // store prefetched regs -> smem (transpose)
        as[q + 0][r] = ha.x; as[q + 1][r] = ha.y;
        as[q + 2][r] = ha.z; as[q + 3][r] = ha.w;
        ws[q + 0][r] = wa.x; ws[q + 1][r] = wa.y;
        ws[q + 2][r] = wa.z; ws[q + 3][r] = wa.w;
        __syncthreads();

        // prefetch next tile
        if (kc + BK < CD) {
            ha = *(const float4*)&hid[(size_t)(b0 + r) * CD + kc + BK + q];
            if (j0 + r < ODIM)
                wa = *(const float4*)&W[(size_t)(j0 + r) * CD + kc + BK + q];
        }

        #pragma unroll
        for (int kk = 0; kk < BK; kk++) {
            float4 av = *(float4*)&as[kk][ty * 4];
            float4 bv = *(float4*)&ws[kk][tx * 4];
            float a[4] = {av.x, av.y, av.z, av.w};
            float b[4] = {bv.x, bv.y, bv.z, bv.w};
            #pragma unroll
            for (int i = 0; i < 4; i++)
                #pragma unroll
                for (int j = 0; j < 4; j++)
                    acc[i][j] += a[i] * b[j];
        }
        __syncthreads();
    }

    #pragma unroll
    for (int i = 0; i < 4; i++) {
        int bb = b0 + ty * 4 + i;
        #pragma unroll
        for (int j = 0; j < 4; j++) {
            int jj = j0 + tx * 4 + j;
            if (jj >= ODIM) continue;
            float v = acc[i][j] + bias[jj];
            float act;
            if (jj < 128)            act = v;                       // k
            else if (jj == 128)      act = softplusf_(v);           // beta
            else if (jj == 129)      act = sigmoidf_(v);            // g
            else if (jj <= 132)      act = v;                       // s raw
            else if (jj == 133)      act = 1.f + softplusf_(v);     // gamma
            else if (jj < 262) {     act = sigmoidf_(v);            // e
                                     g_e[(size_t)bb * Mm + (jj - 134)] = act; }
            else {                   act = v;                       // a
                                     g_a[(size_t)bb * Mm + (jj - 262)] = act; }
            o[(size_t)bb * ODIM + jj] = act;
        }
    }
}

// ------------------------------------------------------------------
// Kernel 2: compute w[b,:] (content + location addressing).
// One CTA per batch row, 512 threads. Reads memory once (256 MB total).
// ------------------------------------------------------------------
__device__ __forceinline__ float block_reduce_sum(float v, float* red) {
    int lane = threadIdx.x & 31, wid = threadIdx.x >> 5;
    #pragma unroll
    for (int off = 16; off; off >>= 1) v += __shfl_xor_sync(0xffffffffu, v, off);
    if (lane == 0) red[wid] = v;
    __syncthreads();
    if (wid == 0) {
        float x = (lane < 16) ? red[lane] : 0.f;
        #pragma unroll
        for (int off = 8; off; off >>= 1) x += __shfl_xor_sync(0xffffffffu, x, off);
        if (lane == 0) red[16] = x;
    }
    __syncthreads();
    float r = red[16];
    __syncthreads();
    return r;
}

__device__ __forceinline__ float block_reduce_max(float v, float* red) {
    int lane = threadIdx.x & 31, wid = threadIdx.x >> 5;
    #pragma unroll
    for (int off = 16; off; off >>= 1)
        v = fmaxf(v, __shfl_xor_sync(0xffffffffu, v, off));
    if (lane == 0) red[wid] = v;
    __syncthreads();
    if (wid == 0) {
        float x = (lane < 16) ? red[lane] : -3.4e38f;
        #pragma unroll
        for (int off = 8; off; off >>= 1)
            x = fmaxf(x, __shfl_xor_sync(0xffffffffu, x, off));
        if (lane == 0) red[16] = x;
    }
    __syncthreads();
    float r = red[16];
    __syncthreads();
    return r;
}

__global__ __launch_bounds__(512, 3) void ntm_w(const float* __restrict__ w_pre,
                                                const float* __restrict__ memory,
                                                float* __restrict__ out_w) {
    __shared__ float k_e[Mm];
    __shared__ float Ksm[Nn];
    __shared__ float wgsm[Nn];
    __shared__ float red[17];
    __shared__ float s_beta, s_g, s_s0, s_s1, s_s2, s_gamma, s_knorm;

    const int b = blockIdx.x;
    const int tid = threadIdx.x;
    const int lane = tid & 31, wid = tid >> 5;
    const float* __restrict__ ob = g_o + (size_t)b * ODIM;

    if (tid < Mm) k_e[tid] = ob[tid] + 1e-16f;
    if (tid == 128) {
        s_beta = ob[128];          // already softplus'd
        s_g    = ob[129];          // already sigmoid'd
        float x0 = ob[130], x1 = ob[131], x2 = ob[132];
        float mx = fmaxf(x0, fmaxf(x1, x2));
        float e0 = expf(x0 - mx), e1 = expf(x1 - mx), e2 = expf(x2 - mx);
        float inv = 1.f / (e0 + e1 + e2);
        s_s0 = e0 * inv; s_s1 = e1 * inv; s_s2 = e2 * inv;
        s_gamma = ob[133];         // already 1+softplus'd
    }
    __syncthreads();

    {
        float v = (tid < Mm) ? k_e[tid] * k_e[tid] : 0.f;
        float ss = block_reduce_sum(v, red);
        if (tid == 0) s_knorm = sqrtf(ss);
        __syncthreads();
    }
    const float knorm = s_knorm;
    const float4 kv = *(const float4*)&k_e[lane * 4];
    const float* __restrict__ memb = memory + (size_t)b * Nn * Mm;

    // cosine similarity: one warp per row, 2 rows in flight (keeps regs <=42)
    #pragma unroll 1
    for (int t = 0; t < 16; t++) {
        int n0 = wid + 32 * t;
        int n1 = n0 + 16;
        float4 m0 = __ldg((const float4*)(memb + (size_t)n0 * Mm) + lane);
        float4 m1 = __ldg((const float4*)(memb + (size_t)n1 * Mm) + lane);
        #pragma unroll
        for (int q = 0; q < 2; q++) {
            float4 m4 = q ? m1 : m0;
            int n = q ? n1 : n0;
            float x0 = m4.x + 1e-16f, x1 = m4.y + 1e-16f;
            float x2 = m4.z + 1e-16f, x3 = m4.w + 1e-16f;
            float num = x0 * kv.x + x1 * kv.y + x2 * kv.z + x3 * kv.w;
            float ss  = x0 * x0 + x1 * x1 + x2 * x2 + x3 * x3;
            #pragma unroll
            for (int off = 16; off; off >>= 1) {
                num += __shfl_xor_sync(0xffffffffu, num, off);
                ss  += __shfl_xor_sync(0xffffffffu, ss, off);
            }
            if (lane == 0) {
                float denom = sqrtf(ss) * knorm;
                Ksm[n] = num / fmaxf(denom, 1e-8f);
            }
        }
    }
    __syncthreads();

    // softmax + interpolate + shift + sharpen + normalize
    const int n = tid;
    float bk = s_beta * Ksm[n];
    float mx = block_reduce_max(bk, red);
    float p = expf(bk - mx);
    float psum = block_reduce_sum(p, red);
    float wc = p / psum;
    float g = s_g;
    float wg = g * wc + (1.f - g) * __ldg(&w_pre[(size_t)b * Nn + n]);
    wgsm[n] = wg;
    __syncthreads();
    float wsh = s_s0 * wgsm[(n + Nn - 1) & (Nn - 1)]
              + s_s1 * wg
              + s_s2 * wgsm[(n + 1) & (Nn - 1)];
    float wsp = powf(wsh, s_gamma);
    float wsum = block_reduce_sum(wsp, red);
    out_w[(size_t)b * Nn + n] = wsp / (wsum + 1e-16f);
}

// ------------------------------------------------------------------
// Kernel 3: erase/add streaming. Warp per row, 4 rows in flight.
// e/a hoisted into registers once per block (block is single-b).
// ------------------------------------------------------------------
__global__ __launch_bounds__(256) void erase_add(const float* __restrict__ memory,
                                                 const float* __restrict__ w,
                                                 float* __restrict__ out_mem) {
    const int b = blockIdx.y;
    const int lane = threadIdx.x & 31;
    const int wp = threadIdx.x >> 5;
    const int n0 = blockIdx.x * 32 + wp * 4;

    const float4 ev = *((const float4*)(g_e + (size_t)b * Mm) + lane);
    const float4 av = *((const float4*)(g_a + (size_t)b * Mm) + lane);
    const float* __restrict__ mb = memory + (size_t)b * Nn * Mm;
    float* __restrict__ omb = out_mem + (size_t)b * Nn * Mm;
    const float* __restrict__ wb = w + (size_t)b * Nn;

    float w0 = __ldg(&wb[n0 + 0]);
    float w1 = __ldg(&wb[n0 + 1]);
    float w2 = __ldg(&wb[n0 + 2]);
    float w3 = __ldg(&wb[n0 + 3]);
    float4 m0 = __ldg((const float4*)(mb + (size_t)(n0 + 0) * Mm) + lane);
    float4 m1 = __ldg((const float4*)(mb + (size_t)(n0 + 1) * Mm) + lane);
    float4 m2 = __ldg((const float4*)(mb + (size_t)(n0 + 2) * Mm) + lane);
    float4 m3 = __ldg((const float4*)(mb + (size_t)(n0 + 3) * Mm) + lane);

    float4 r;
    r.x = m0.x * (1.f - w0 * ev.x) + w0 * av.x;
    r.y = m0.y * (1.f - w0 * ev.y) + w0 * av.y;
    r.z = m0.z * (1.f - w0 * ev.z) + w0 * av.z;
    r.w = m0.w * (1.f - w0 * ev.w) + w0 * av.w;
    *((float4*)(omb + (size_t)(n0 + 0) * Mm) + lane) = r;
    r.x = m1.x * (1.f - w1 * ev.x) + w1 * av.x;
    r.y = m1.y * (1.f - w1 * ev.y) + w1 * av.y;
    r.z = m1.z * (1.f - w1 * ev.z) + w1 * av.z;
    r.w = m1.w * (1.f - w1 * ev.w) + w1 * av.w;
    *((float4*)(omb + (size_t)(n0 + 1) * Mm) + lane) = r;
    r.x = m2.x * (1.f - w2 * ev.x) + w2 * av.x;
    r.y = m2.y * (1.f - w2 * ev.y) + w2 * av.y;
    r.z = m2.z * (1.f - w2 * ev.z) + w2 * av.z;
    r.w = m2.w * (1.f - w2 * ev.w) + w2 * av.w;
    *((float4*)(omb + (size_t)(n0 + 2) * Mm) + lane) = r;
    r.x = m3.x * (1.f - w3 * ev.x) + w3 * av.x;
    r.y = m3.y * (1.f - w3 * ev.y) + w3 * av.y;
    r.z = m3.z * (1.f - w3 * ev.z) + w3 * av.z;
    r.w = m3.w * (1.f - w3 * ev.w) + w3 * av.w;
    *((float4*)(omb + (size_t)(n0 + 3) * Mm) + lane) = r;
}

// ------------------------------------------------------------------
extern "C" void kernel_launch(void* const* d_in, const int* in_sizes, int n_in,
                              void* d_out, int out_size) {
    const float* hid    = (const float*)d_in[0];
    const float* w_pre  = (const float*)d_in[1];
    const float* memory = (const float*)d_in[2];
    const float* W_fc   = (const float*)d_in[3];
    const float* b_fc   = (const float*)d_in[4];
    float* out = (float*)d_out;
    float* out_w   = out;
    float* out_mem = out + (size_t)Bb * Nn;

    float* o_ptr = nullptr;
    cudaGetSymbolAddress((void**)&o_ptr, g_o);

    fc_gemm<<<dim3(Bb / BM, (ODIM + BN - 1) / BN), 256>>>(hid, W_fc, b_fc, o_ptr);
    ntm_w<<<Bb, 512>>>(w_pre, memory, out_w);
    erase_add<<<dim3(Nn / 32, Bb), 256>>>(memory, out_w, out_mem);
}

// round 3
// speedup vs baseline: 1.1156x; 1.0580x over previous
#include <cuda_runtime.h>

#define Bb   1024
#define Nn   512
#define Mm   128
#define CD   1024
#define ODIM 390
#define KSPLIT 4
#define KCH  (CD / KSPLIT)
#define CACHE_ROWS 416          // rows of memory cached in smem per CTA

// scratch (allowed: __device__ global arrays)
__device__ float g_part[KSPLIT * Bb * ODIM];   // split-K partial sums

__device__ __forceinline__ float sigmoidf_(float x) { return 1.f / (1.f + expf(-x)); }
__device__ __forceinline__ float softplusf_(float x) {
    return fmaxf(x, 0.f) + log1pf(expf(-fabsf(x)));
}

// ------------------------------------------------------------------
// Kernel 1: split-K GEMM partials.  part[z] = hid[:, zK:(z+1)K] @ W[:, zK:]^T
// BM=BN=64, BK=16, 256 threads, 4x4 microtile, reg double-buffer.
// ------------------------------------------------------------------
#define BM 64
#define BN 64
#define BK 16

__global__ __launch_bounds__(256) void fc_gemm(const float* __restrict__ hid,
                                               const float* __restrict__ W) {
    __shared__ float as[BK][BM + 4];
    __shared__ float ws[BK][BN + 4];

    const int b0 = blockIdx.x * BM;
    const int j0 = blockIdx.y * BN;
    const int z  = blockIdx.z;
    const int k0 = z * KCH;
    const int tid = threadIdx.x;
    const int ty = tid >> 4;
    const int tx = tid & 15;
    const int r  = tid >> 2;
    const int q  = (tid & 3) * 4;

    float acc[4][4] = {};

    float4 ha = *(const float4*)&hid[(size_t)(b0 + r) * CD + k0 + q];
    float4 wa = make_float4(0.f, 0.f, 0.f, 0.f);
    if (j0 + r < ODIM)
        wa = *(const float4*)&W[(size_t)(j0 + r) * CD + k0 + q];

    for (int kc = 0; kc < KCH; kc += BK) {
        as[q + 0][r] = ha.x; as[q + 1][r] = ha.y;
        as[q + 2][r] = ha.z; as[q + 3][r] = ha.w;
        ws[q + 0][r] = wa.x; ws[q + 1][r] = wa.y;
        ws[q + 2][r] = wa.z; ws[q + 3][r] = wa.w;
        __syncthreads();

        if (kc + BK < KCH) {
            ha = *(const float4*)&hid[(size_t)(b0 + r) * CD + k0 + kc + BK + q];
            if (j0 + r < ODIM)
                wa = *(const float4*)&W[(size_t)(j0 + r) * CD + k0 + kc + BK + q];
        }

        #pragma unroll
        for (int kk = 0; kk < BK; kk++) {
            float4 av = *(float4*)&as[kk][ty * 4];
            float4 bv = *(float4*)&ws[kk][tx * 4];
            float a[4] = {av.x, av.y, av.z, av.w};
            float b[4] = {bv.x, bv.y, bv.z, bv.w};
            #pragma unroll
            for (int i = 0; i < 4; i++)
                #pragma unroll
                for (int j = 0; j < 4; j++)
                    acc[i][j] += a[i] * b[j];
        }
        __syncthreads();
    }

    float* __restrict__ op = g_part + (size_t)z * Bb * ODIM;
    #pragma unroll
    for (int i = 0; i < 4; i++) {
        int bb = b0 + ty * 4 + i;
        #pragma unroll
        for (int j = 0; j < 4; j++) {
            int jj = j0 + tx * 4 + j;
            if (jj < ODIM)
                op[(size_t)bb * ODIM + jj] = acc[i][j];
        }
    }
}

// ------------------------------------------------------------------
// Kernel 2: fully fused NTM write head, one CTA per b, 512 threads.
// memory rows [0, CACHE_ROWS) cached in dynamic smem between passes.
// ------------------------------------------------------------------
__device__ __forceinline__ float block_reduce_sum(float v, float* red) {
    int lane = threadIdx.x & 31, wid = threadIdx.x >> 5;
    #pragma unroll
    for (int off = 16; off; off >>= 1) v += __shfl_xor_sync(0xffffffffu, v, off);
    if (lane == 0) red[wid] = v;
    __syncthreads();
    if (wid == 0) {
        float x = (lane < 16) ? red[lane] : 0.f;
        #pragma unroll
        for (int off = 8; off; off >>= 1) x += __shfl_xor_sync(0xffffffffu, x, off);
        if (lane == 0) red[16] = x;
    }
    __syncthreads();
    float r = red[16];
    __syncthreads();
    return r;
}

__device__ __forceinline__ float block_reduce_max(float v, float* red) {
    int lane = threadIdx.x & 31, wid = threadIdx.x >> 5;
    #pragma unroll
    for (int off = 16; off; off >>= 1)
        v = fmaxf(v, __shfl_xor_sync(0xffffffffu, v, off));
    if (lane == 0) red[wid] = v;
    __syncthreads();
    if (wid == 0) {
        float x = (lane < 16) ? red[lane] : -3.4e38f;
        #pragma unroll
        for (int off = 8; off; off >>= 1)
            x = fmaxf(x, __shfl_xor_sync(0xffffffffu, x, off));
        if (lane == 0) red[16] = x;
    }
    __syncthreads();
    float r = red[16];
    __syncthreads();
    return r;
}

__global__ __launch_bounds__(512, 1) void ntm_fused(const float* __restrict__ w_pre,
                                                    const float* __restrict__ memory,
                                                    const float* __restrict__ bias,
                                                    float* __restrict__ out_w,
                                                    float* __restrict__ out_mem) {
    extern __shared__ float smem[];
    float* cache = smem;                           // CACHE_ROWS * 128
    float* Ksm   = smem + CACHE_ROWS * Mm;         // 512 (K, later final w)
    float* wgsm  = Ksm + Nn;                       // 512
    float* k_e   = wgsm + Nn;                      // 128
    float* evec  = k_e + Mm;                       // 128
    float* avec  = evec + Mm;                      // 128
    float* red   = avec + Mm;                      // 32

    __shared__ float s_beta, s_g, s_s0, s_s1, s_s2, s_gamma, s_knorm;
    __shared__ float s_raw[3];

    const int b = blockIdx.x;
    const int tid = threadIdx.x;
    const int lane = tid & 31, wid = tid >> 5;

    // ---- phase 0: reduce split-K partials + activations ----
    if (tid < ODIM) {
        const size_t off = (size_t)b * ODIM + tid;
        float v = bias[tid] + g_part[off]
                + g_part[(size_t)1 * Bb * ODIM + off]
                + g_part[(size_t)2 * Bb * ODIM + off]
                + g_part[(size_t)3 * Bb * ODIM + off];
        int j = tid;
        if (j < 128)            k_e[j] = v + 1e-16f;
        else if (j == 128)      s_beta = softplusf_(v);
        else if (j == 129)      s_g    = sigmoidf_(v);
        else if (j <= 132)      s_raw[j - 130] = v;
        else if (j == 133)      s_gamma = 1.f + softplusf_(v);
        else if (j < 262)       evec[j - 134] = sigmoidf_(v);
        else                    avec[j - 262] = v;
    }
    __syncthreads();
    if (tid == 0) {
        float x0 = s_raw[0], x1 = s_raw[1], x2 = s_raw[2];
        float mx = fmaxf(x0, fmaxf(x1, x2));
        float e0 = expf(x0 - mx), e1 = expf(x1 - mx), e2 = expf(x2 - mx);
        float inv = 1.f / (e0 + e1 + e2);
        s_s0 = e0 * inv; s_s1 = e1 * inv; s_s2 = e2 * inv;
    }
    {   // ||k + eps||
        float v = (tid < Mm) ? k_e[tid] * k_e[tid] : 0.f;
        float ss = block_reduce_sum(v, red);
        if (tid == 0) s_knorm = sqrtf(ss);
        __syncthreads();
    }
    const float knorm = s_knorm;
    const float4 kv = *(const float4*)&k_e[lane * 4];
    const float* __restrict__ memb = memory + (size_t)b * Nn * Mm;

    // ---- phase 1: cosine sim, warp per row, 4 rows in flight; cache rows ----
    const int n_base = wid * 32;
    #pragma unroll 1
    for (int i = 0; i < 32; i += 4) {
        const int n = n_base + i;
        float4 m0 = __ldg((const float4*)(memb + (size_t)(n + 0) * Mm) + lane);
        float4 m1 = __ldg((const float4*)(memb + (size_t)(n + 1) * Mm) + lane);
        float4 m2 = __ldg((const float4*)(memb + (size_t)(n + 2) * Mm) + lane);
        float4 m3 = __ldg((const float4*)(memb + (size_t)(n + 3) * Mm) + lane);
        if (n < CACHE_ROWS) {   // uniform per warp (CACHE_ROWS % 32 == 0)
            *((float4*)(cache + (size_t)(n + 0) * Mm) + lane) = m0;
            *((float4*)(cache + (size_t)(n + 1) * Mm) + lane) = m1;
            *((float4*)(cache + (size_t)(n + 2) * Mm) + lane) = m2;
            *((float4*)(cache + (size_t)(n + 3) * Mm) + lane) = m3;
        }
        #pragma unroll
        for (int qq = 0; qq < 4; qq++) {
            float4 m4 = (qq == 0) ? m0 : (qq == 1) ? m1 : (qq == 2) ? m2 : m3;
            float x0 = m4.x + 1e-16f, x1 = m4.y + 1e-16f;
            float x2 = m4.z + 1e-16f, x3 = m4.w + 1e-16f;
            float num = x0 * kv.x + x1 * kv.y + x2 * kv.z + x3 * kv.w;
            float ss  = x0 * x0 + x1 * x1 + x2 * x2 + x3 * x3;
            #pragma unroll
            for (int off = 16; off; off >>= 1) {
                num += __shfl_xor_sync(0xffffffffu, num, off);
                ss  += __shfl_xor_sync(0xffffffffu, ss, off);
            }
            if (lane == 0) {
                float denom = sqrtf(ss) * knorm;
                Ksm[n + qq] = num / fmaxf(denom, 1e-8f);
            }
        }
    }
    __syncthreads();

    // ---- phase 2: softmax + interpolate + shift + sharpen + normalize ----
    const int n = tid;
    float bk = s_beta * Ksm[n];
    float mx = block_reduce_max(bk, red);
    float p = expf(bk - mx);
    float psum = block_reduce_sum(p, red);
    float wc = p / psum;
    float g = s_g;
    float wg = g * wc + (1.f - g) * __ldg(&w_pre[(size_t)b * Nn + n]);
    wgsm[n] = wg;
    __syncthreads();
    float wsh = s_s0 * wgsm[(n + Nn - 1) & (Nn - 1)]
              + s_s1 * wg
              + s_s2 * wgsm[(n + 1) & (Nn - 1)];
    float wsp = powf(wsh, s_gamma);
    float wsum = block_reduce_sum(wsp, red);
    float w = wsp / (wsum + 1e-16f);
    out_w[(size_t)b * Nn + n] = w;
    Ksm[n] = w;                 // final w for phase 3
    __syncthreads();

    // ---- phase 3: erase/add write ----
    const float4 ev = *((const float4*)evec + lane);
    const float4 av = *((const float4*)avec + lane);
    float* __restrict__ omb = out_mem + (size_t)b * Nn * Mm;

    if (n_base + 32 <= CACHE_ROWS) {
        // smem-cached rows
        #pragma unroll 4
        for (int i = 0; i < 32; i++) {
            const int nr = n_base + i;
            float wn = Ksm[nr];
            float4 mv = *((const float4*)(cache + (size_t)nr * Mm) + lane);
            float4 r;
            r.x = mv.x * (1.f - wn * ev.x) + wn * av.x;
            r.y = mv.y * (1.f - wn * ev.y) + wn * av.y;
            r.z = mv.z * (1.f - wn * ev.z) + wn * av.z;
            r.w = mv.w * (1.f - wn * ev.w) + wn * av.w;
            *((float4*)(omb + (size_t)nr * Mm) + lane) = r;
        }
    } else {
        // global re-read rows (expect mostly L2 hits), 4 in flight
        #pragma unroll 1
        for (int i = 0; i < 32; i += 4) {
            const int nr = n_base + i;
            float4 m0 = __ldg((const float4*)(memb + (size_t)(nr + 0) * Mm) + lane);
            float4 m1 = __ldg((const float4*)(memb + (size_t)(nr + 1) * Mm) + lane);
            float4 m2 = __ldg((const float4*)(memb + (size_t)(nr + 2) * Mm) + lane);
            float4 m3 = __ldg((const float4*)(memb + (size_t)(nr + 3) * Mm) + lane);
            #pragma unroll
            for (int qq = 0; qq < 4; qq++) {
                float4 mv = (qq == 0) ? m0 : (qq == 1) ? m1 : (qq == 2) ? m2 : m3;
                float wn = Ksm[nr + qq];
                float4 r;
                r.x = mv.x * (1.f - wn * ev.x) + wn * av.x;
                r.y = mv.y * (1.f - wn * ev.y) + wn * av.y;
                r.z = mv.z * (1.f - wn * ev.z) + wn * av.z;
                r.w = mv.w * (1.f - wn * ev.w) + wn * av.w;
                *((float4*)(omb + (size_t)(nr + qq) * Mm) + lane) = r;
            }
        }
    }
}

// ------------------------------------------------------------------
extern "C" void kernel_launch(void* const* d_in, const int* in_sizes, int n_in,
                              void* d_out, int out_size) {
    const float* hid    = (const float*)d_in[0];
    const float* w_pre  = (const float*)d_in[1];
    const float* memory = (const float*)d_in[2];
    const float* W_fc   = (const float*)d_in[3];
    const float* b_fc   = (const float*)d_in[4];
    float* out = (float*)d_out;
    float* out_w   = out;
    float* out_mem = out + (size_t)Bb * Nn;

    const int dyn_smem = (CACHE_ROWS * Mm + Nn + Nn + Mm + Mm + Mm + 32) * 4;
    static bool attr_set = false;
    if (!attr_set) {
        cudaFuncSetAttribute(ntm_fused, cudaFuncAttributeMaxDynamicSharedMemorySize,
                             dyn_smem);
        attr_set = true;
    }

    fc_gemm<<<dim3(Bb / BM, (ODIM + BN - 1) / BN, KSPLIT), 256>>>(hid, W_fc);
    ntm_fused<<<Bb, 512, dyn_smem>>>(w_pre, memory, b_fc, out_w, out_mem);
}

// round 4
// speedup vs baseline: 1.4390x; 1.2899x over previous
#include <cuda_runtime.h>

#define Bb   1024
#define Nn   512
#define Mm   128
#define CD   1024
#define ODIM 390
#define KSPLIT 4
#define KCH  (CD / KSPLIT)
#define CACHE_ROWS 192          // rows cached in smem per CTA (6 warps' worth)

// scratch (allowed: __device__ global arrays)
__device__ float g_part[KSPLIT * Bb * ODIM];   // split-K partial sums

__device__ __forceinline__ float sigmoidf_(float x) { return 1.f / (1.f + expf(-x)); }
__device__ __forceinline__ float softplusf_(float x) {
    return fmaxf(x, 0.f) + log1pf(expf(-fabsf(x)));
}

// ------------------------------------------------------------------
// Kernel 1: split-K GEMM partials (unchanged from R3 — measured ~30us)
// ------------------------------------------------------------------
#define BM 64
#define BN 64
#define BK 16

__global__ __launch_bounds__(256) void fc_gemm(const float* __restrict__ hid,
                                               const float* __restrict__ W) {
    __shared__ float as[BK][BM + 4];
    __shared__ float ws[BK][BN + 4];

    const int b0 = blockIdx.x * BM;
    const int j0 = blockIdx.y * BN;
    const int z  = blockIdx.z;
    const int k0 = z * KCH;
    const int tid = threadIdx.x;
    const int ty = tid >> 4;
    const int tx = tid & 15;
    const int r  = tid >> 2;
    const int q  = (tid & 3) * 4;

    float acc[4][4] = {};

    float4 ha = *(const float4*)&hid[(size_t)(b0 + r) * CD + k0 + q];
    float4 wa = make_float4(0.f, 0.f, 0.f, 0.f);
    if (j0 + r < ODIM)
        wa = *(const float4*)&W[(size_t)(j0 + r) * CD + k0 + q];

    for (int kc = 0; kc < KCH; kc += BK) {
        as[q + 0][r] = ha.x; as[q + 1][r] = ha.y;
        as[q + 2][r] = ha.z; as[q + 3][r] = ha.w;
        ws[q + 0][r] = wa.x; ws[q + 1][r] = wa.y;
        ws[q + 2][r] = wa.z; ws[q + 3][r] = wa.w;
        __syncthreads();

        if (kc + BK < KCH) {
            ha = *(const float4*)&hid[(size_t)(b0 + r) * CD + k0 + kc + BK + q];
            if (j0 + r < ODIM)
                wa = *(const float4*)&W[(size_t)(j0 + r) * CD + k0 + kc + BK + q];
        }

        #pragma unroll
        for (int kk = 0; kk < BK; kk++) {
            float4 av = *(float4*)&as[kk][ty * 4];
            float4 bv = *(float4*)&ws[kk][tx * 4];
            float a[4] = {av.x, av.y, av.z, av.w};
            float b[4] = {bv.x, bv.y, bv.z, bv.w};
            #pragma unroll
            for (int i = 0; i < 4; i++)
                #pragma unroll
                for (int j = 0; j < 4; j++)
                    acc[i][j] += a[i] * b[j];
        }
        __syncthreads();
    }

    float* __restrict__ op = g_part + (size_t)z * Bb * ODIM;
    #pragma unroll
    for (int i = 0; i < 4; i++) {
        int bb = b0 + ty * 4 + i;
        #pragma unroll
        for (int j = 0; j < 4; j++) {
            int jj = j0 + tx * 4 + j;
            if (jj < ODIM)
                op[(size_t)bb * ODIM + jj] = acc[i][j];
        }
    }
}

// ------------------------------------------------------------------
// Kernel 2: fused NTM write head. 192-row smem cache -> 2 CTAs/SM.
// ------------------------------------------------------------------
__device__ __forceinline__ float block_reduce_sum(float v, float* red) {
    int lane = threadIdx.x & 31, wid = threadIdx.x >> 5;
    #pragma unroll
    for (int off = 16; off; off >>= 1) v += __shfl_xor_sync(0xffffffffu, v, off);
    if (lane == 0) red[wid] = v;
    __syncthreads();
    if (wid == 0) {
        float x = (lane < 16) ? red[lane] : 0.f;
        #pragma unroll
        for (int off = 8; off; off >>= 1) x += __shfl_xor_sync(0xffffffffu, x, off);
        if (lane == 0) red[16] = x;
    }
    __syncthreads();
    float r = red[16];
    __syncthreads();
    return r;
}

__device__ __forceinline__ float block_reduce_max(float v, float* red) {
    int lane = threadIdx.x & 31, wid = threadIdx.x >> 5;
    #pragma unroll
    for (int off = 16; off; off >>= 1)
        v = fmaxf(v, __shfl_xor_sync(0xffffffffu, v, off));
    if (lane == 0) red[wid] = v;
    __syncthreads();
    if (wid == 0) {
        float x = (lane < 16) ? red[lane] : -3.4e38f;
        #pragma unroll
        for (int off = 8; off; off >>= 1)
            x = fmaxf(x, __shfl_xor_sync(0xffffffffu, x, off));
        if (lane == 0) red[16] = x;
    }
    __syncthreads();
    float r = red[16];
    __syncthreads();
    return r;
}

__global__ __launch_bounds__(512, 2) void ntm_fused(const float* __restrict__ w_pre,
                                                    const float* __restrict__ memory,
                                                    const float* __restrict__ bias,
                                                    float* __restrict__ out_w,
                                                    float* __restrict__ out_mem) {
    extern __shared__ float smem[];
    float* cache = smem;                           // CACHE_ROWS * 128
    float* Ksm   = smem + CACHE_ROWS * Mm;         // 512 (K, later final w)
    float* wgsm  = Ksm + Nn;                       // 512
    float* k_e   = wgsm + Nn;                      // 128
    float* evec  = k_e + Mm;                       // 128
    float* avec  = evec + Mm;                      // 128
    float* red   = avec + Mm;                      // 32

    __shared__ float s_beta, s_g, s_s0, s_s1, s_s2, s_gamma, s_knorm;
    __shared__ float s_raw[3];

    const int b = blockIdx.x;
    const int tid = threadIdx.x;
    const int lane = tid & 31, wid = tid >> 5;

    // ---- phase 0: reduce split-K partials + activations ----
    if (tid < ODIM) {
        const size_t off = (size_t)b * ODIM + tid;
        float v = bias[tid] + g_part[off]
                + g_part[(size_t)1 * Bb * ODIM + off]
                + g_part[(size_t)2 * Bb * ODIM + off]
                + g_part[(size_t)3 * Bb * ODIM + off];
        int j = tid;
        if (j < 128)            k_e[j] = v + 1e-16f;
        else if (j == 128)      s_beta = softplusf_(v);
        else if (j == 129)      s_g    = sigmoidf_(v);
        else if (j <= 132)      s_raw[j - 130] = v;
        else if (j == 133)      s_gamma = 1.f + softplusf_(v);
        else if (j < 262)       evec[j - 134] = sigmoidf_(v);
        else                    avec[j - 262] = v;
    }
    __syncthreads();
    if (tid == 0) {
        float x0 = s_raw[0], x1 = s_raw[1], x2 = s_raw[2];
        float mx = fmaxf(x0, fmaxf(x1, x2));
        float e0 = expf(x0 - mx), e1 = expf(x1 - mx), e2 = expf(x2 - mx);
        float inv = 1.f / (e0 + e1 + e2);
        s_s0 = e0 * inv; s_s1 = e1 * inv; s_s2 = e2 * inv;
    }
    {   // ||k + eps||
        float v = (tid < Mm) ? k_e[tid] * k_e[tid] : 0.f;
        float ss = block_reduce_sum(v, red);
        if (tid == 0) s_knorm = sqrtf(ss);
        __syncthreads();
    }
    const float knorm = s_knorm;
    const float4 kv = *(const float4*)&k_e[lane * 4];
    const float* __restrict__ memb = memory + (size_t)b * Nn * Mm;

    // ---- phase 1: cosine sim, warp per row, 4 rows in flight ----
    const int n_base = wid * 32;
    const bool cached = (n_base < CACHE_ROWS);   // uniform per warp
    #pragma unroll 1
    for (int i = 0; i < 32; i += 4) {
        const int n = n_base + i;
        float4 m0, m1, m2, m3;
        if (cached) {
            // evict-first: these bytes live in smem afterwards
            m0 = __ldcs((const float4*)(memb + (size_t)(n + 0) * Mm) + lane);
            m1 = __ldcs((const float4*)(memb + (size_t)(n + 1) * Mm) + lane);
            m2 = __ldcs((const float4*)(memb + (size_t)(n + 2) * Mm) + lane);
            m3 = __ldcs((const float4*)(memb + (size_t)(n + 3) * Mm) + lane);
            *((float4*)(cache + (size_t)(n + 0) * Mm) + lane) = m0;
            *((float4*)(cache + (size_t)(n + 1) * Mm) + lane) = m1;
            *((float4*)(cache + (size_t)(n + 2) * Mm) + lane) = m2;
            *((float4*)(cache + (size_t)(n + 3) * Mm) + lane) = m3;
        } else {
            // keep in L2 for phase-3 re-read
            m0 = __ldg((const float4*)(memb + (size_t)(n + 0) * Mm) + lane);
            m1 = __ldg((const float4*)(memb + (size_t)(n + 1) * Mm) + lane);
            m2 = __ldg((const float4*)(memb + (size_t)(n + 2) * Mm) + lane);
            m3 = __ldg((const float4*)(memb + (size_t)(n + 3) * Mm) + lane);
        }
        #pragma unroll
        for (int qq = 0; qq < 4; qq++) {
            float4 m4 = (qq == 0) ? m0 : (qq == 1) ? m1 : (qq == 2) ? m2 : m3;
            float x0 = m4.x + 1e-16f, x1 = m4.y + 1e-16f;
            float x2 = m4.z + 1e-16f, x3 = m4.w + 1e-16f;
            float num = x0 * kv.x + x1 * kv.y + x2 * kv.z + x3 * kv.w;
            float ss  = x0 * x0 + x1 * x1 + x2 * x2 + x3 * x3;
            #pragma unroll
            for (int off = 16; off; off >>= 1) {
                num += __shfl_xor_sync(0xffffffffu, num, off);
                ss  += __shfl_xor_sync(0xffffffffu, ss, off);
            }
            if (lane == 0) {
                float denom = sqrtf(ss) * knorm;
                Ksm[n + qq] = num / fmaxf(denom, 1e-8f);
            }
        }
    }
    __syncthreads();

    // ---- phase 2: softmax + interpolate + shift + sharpen + normalize ----
    const int n = tid;
    float bk = s_beta * Ksm[n];
    float mx = block_reduce_max(bk, red);
    float p = expf(bk - mx);
    float psum = block_reduce_sum(p, red);
    float wc = p / psum;
    float g = s_g;
    float wg = g * wc + (1.f - g) * __ldg(&w_pre[(size_t)b * Nn + n]);
    wgsm[n] = wg;
    __syncthreads();
    float wsh = s_s0 * wgsm[(n + Nn - 1) & (Nn - 1)]
              + s_s1 * wg
              + s_s2 * wgsm[(n + 1) & (Nn - 1)];
    float wsp = powf(wsh, s_gamma);
    float wsum = block_reduce_sum(wsp, red);
    float w = wsp / (wsum + 1e-16f);
    out_w[(size_t)b * Nn + n] = w;
    Ksm[n] = w;                 // final w for phase 3
    __syncthreads();

    // ---- phase 3: erase/add write ----
    const float4 ev = *((const float4*)evec + lane);
    const float4 av = *((const float4*)avec + lane);
    float* __restrict__ omb = out_mem + (size_t)b * Nn * Mm;

    if (cached) {
        #pragma unroll 4
        for (int i = 0; i < 32; i++) {
            const int nr = n_base + i;
            float wn = Ksm[nr];
            float4 mv = *((const float4*)(cache + (size_t)nr * Mm) + lane);
            float4 r;
            r.x = mv.x * (1.f - wn * ev.x) + wn * av.x;
            r.y = mv.y * (1.f - wn * ev.y) + wn * av.y;
            r.z = mv.z * (1.f - wn * ev.z) + wn * av.z;
            r.w = mv.w * (1.f - wn * ev.w) + wn * av.w;
            __stcs((float4*)(omb + (size_t)nr * Mm) + lane, r);
        }
    } else {
        #pragma unroll 1
        for (int i = 0; i < 32; i += 4) {
            const int nr = n_base + i;
            float4 m0 = __ldcs((const float4*)(memb + (size_t)(nr + 0) * Mm) + lane);
            float4 m1 = __ldcs((const float4*)(memb + (size_t)(nr + 1) * Mm) + lane);
            float4 m2 = __ldcs((const float4*)(memb + (size_t)(nr + 2) * Mm) + lane);
            float4 m3 = __ldcs((const float4*)(memb + (size_t)(nr + 3) * Mm) + lane);
            #pragma unroll
            for (int qq = 0; qq < 4; qq++) {
                float4 mv = (qq == 0) ? m0 : (qq == 1) ? m1 : (qq == 2) ? m2 : m3;
                float wn = Ksm[nr + qq];
                float4 r;
                r.x = mv.x * (1.f - wn * ev.x) + wn * av.x;
                r.y = mv.y * (1.f - wn * ev.y) + wn * av.y;
                r.z = mv.z * (1.f - wn * ev.z) + wn * av.z;
                r.w = mv.w * (1.f - wn * ev.w) + wn * av.w;
                __stcs((float4*)(omb + (size_t)(nr + qq) * Mm) + lane, r);
            }
        }
    }
}

// ------------------------------------------------------------------
extern "C" void kernel_launch(void* const* d_in, const int* in_sizes, int n_in,
                              void* d_out, int out_size) {
    const float* hid    = (const float*)d_in[0];
    const float* w_pre  = (const float*)d_in[1];
    const float* memory = (const float*)d_in[2];
    const float* W_fc   = (const float*)d_in[3];
    const float* b_fc   = (const float*)d_in[4];
    float* out = (float*)d_out;
    float* out_w   = out;
    float* out_mem = out + (size_t)Bb * Nn;

    const int dyn_smem = (CACHE_ROWS * Mm + Nn + Nn + Mm + Mm + Mm + 32) * 4;
    static bool attr_set = false;
    if (!attr_set) {
        cudaFuncSetAttribute(ntm_fused, cudaFuncAttributeMaxDynamicSharedMemorySize,
                             dyn_smem);
        attr_set = true;
    }

    fc_gemm<<<dim3(Bb / BM, (ODIM + BN - 1) / BN, KSPLIT), 256>>>(hid, W_fc);
    ntm_fused<<<Bb, 512, dyn_smem>>>(w_pre, memory, b_fc, out_w, out_mem);
}